// round 8
// baseline (speedup 1.0000x reference)
#include <cuda_runtime.h>
#include <cuda_bf16.h>
#include <cstdint>

#define BN 1024
#define TT 128
#define DIN 32
#define HH 512
#define DD2 256
#define DOUT 16
#define GG 1536

typedef unsigned int u32;
typedef unsigned long long u64;

// ---------------- device globals (static scratch; no allocation) ----------------
__device__ float g_Weff[HH*DIN];
__device__ float g_beff[HH];
__device__ float g_Wg[GG*DIN];     // folded input weight (1536 x 32)
__device__ float g_bg[GG];         // folded input bias
__device__ float g_hf[BN*HH];      // fp32 hidden state
__device__ float g_out2[BN*DD2];
__device__ __align__(16) __nv_bfloat16 g_Ahi[2*BN*HH];   // h planes, ping-pong
__device__ __align__(16) __nv_bfloat16 g_Alo[2*BN*HH];
__device__ __align__(16) __nv_bfloat16 g_Xhi[TT*BN*DIN]; // input planes, t-major
__device__ __align__(16) __nv_bfloat16 g_Xlo[TT*BN*DIN];
__device__ __align__(16) __nv_bfloat16 g_Bhhi[GG*HH];    // W_hh planes (row-major g,k)
__device__ __align__(16) __nv_bfloat16 g_Bhlo[GG*HH];
__device__ __align__(16) __nv_bfloat16 g_Bxhi[GG*DIN];   // Wg planes
__device__ __align__(16) __nv_bfloat16 g_Bxlo[GG*DIN];

// ---------------- helpers ----------------
__device__ __forceinline__ float sigm(float x){
    float e; asm("ex2.approx.f32 %0, %1;" : "=f"(e) : "f"(-1.4426950408889634f*x));
    float r; asm("rcp.approx.f32 %0, %1;" : "=f"(r) : "f"(1.0f + e));
    return r;
}
__device__ __forceinline__ float tanh_(float x){ return 2.0f*sigm(2.0f*x) - 1.0f; }

__device__ __forceinline__ u32 smem_u32(const void* p){
    u32 a; asm("{ .reg .u64 t; cvta.to.shared.u64 t, %1; cvt.u32.u64 %0, t; }" : "=r"(a) : "l"(p));
    return a;
}
__device__ __forceinline__ void mma_bf16(float* d, const u32* a, const u32* b){
    asm volatile("mma.sync.aligned.m16n8k16.row.col.f32.bf16.bf16.f32 "
        "{%0,%1,%2,%3}, {%4,%5,%6,%7}, {%8,%9}, {%0,%1,%2,%3};"
        : "+f"(d[0]), "+f"(d[1]), "+f"(d[2]), "+f"(d[3])
        : "r"(a[0]), "r"(a[1]), "r"(a[2]), "r"(a[3]), "r"(b[0]), "r"(b[1]));
}
__device__ __forceinline__ void ldm_x4(u32* r, u32 addr){
    asm volatile("ldmatrix.sync.aligned.m8n8.x4.shared.b16 {%0,%1,%2,%3}, [%4];"
        : "=r"(r[0]),"=r"(r[1]),"=r"(r[2]),"=r"(r[3]) : "r"(addr));
}
__device__ __forceinline__ void ldm_x2(u32* r, u32 addr){
    asm volatile("ldmatrix.sync.aligned.m8n8.x2.shared.b16 {%0,%1}, [%2];"
        : "=r"(r[0]),"=r"(r[1]) : "r"(addr));
}
__device__ __forceinline__ void cp16(u32 saddr, const void* g){
    asm volatile("cp.async.cg.shared.global [%0], [%1], 16;" :: "r"(saddr), "l"(g));
}
#define CP_COMMIT() asm volatile("cp.async.commit_group;" ::: "memory")
#define CP_WAIT(n)  asm volatile("cp.async.wait_group %0;" :: "n"(n) : "memory")

__device__ __forceinline__ void split_bf16(float v, __nv_bfloat16 &hi, __nv_bfloat16 &lo){
    hi = __float2bfloat16(v);
    lo = __float2bfloat16(v - __bfloat162float(hi));
}

// ---------------- weight folding ----------------
__global__ void fold1(const float* __restrict__ W2, const float* __restrict__ W1,
                      const float* __restrict__ b1, const float* __restrict__ b2)
{
    int i = blockIdx.x, k = threadIdx.x;
    float acc = 0.f, pb = 0.f;
    for (int j = 0; j < DD2; ++j) acc += W2[i*DD2 + j] * W1[j*DIN + k];
    for (int j = k; j < DD2; j += 32) pb += W2[i*DD2 + j]*b1[j];
    g_Weff[i*DIN + k] = acc;
    #pragma unroll
    for (int o = 16; o; o >>= 1) pb += __shfl_down_sync(0xffffffffu, pb, o);
    if (k == 0) g_beff[i] = pb + b2[i];
}
__global__ void fold2(const float* __restrict__ Wih, const float* __restrict__ bih)
{
    int g = blockIdx.x, k = threadIdx.x;
    float acc = 0.f, pb = 0.f;
    for (int i = 0; i < HH; ++i) acc += Wih[g*HH + i] * g_Weff[i*DIN + k];
    for (int i = k; i < HH; i += 32) pb += Wih[g*HH + i]*g_beff[i];
    g_Wg[g*DIN + k] = acc;
    #pragma unroll
    for (int o = 16; o; o >>= 1) pb += __shfl_down_sync(0xffffffffu, pb, o);
    if (k == 0) g_bg[g] = pb + bih[g];
}
__global__ void packBh(const float* __restrict__ Whh){
    int i = blockIdx.x*blockDim.x + threadIdx.x;
    if (i < GG*HH){ __nv_bfloat16 h,l; split_bf16(Whh[i], h, l); g_Bhhi[i]=h; g_Bhlo[i]=l; }
}
__global__ void packBx(){
    int i = blockIdx.x*blockDim.x + threadIdx.x;
    if (i < GG*DIN){ __nv_bfloat16 h,l; split_bf16(g_Wg[i], h, l); g_Bxhi[i]=h; g_Bxlo[i]=l; }
}
__global__ void packX(const float* __restrict__ input){
    int i = blockIdx.x*blockDim.x + threadIdx.x;      // t-major index
    if (i < TT*BN*DIN){
        int k = i & (DIN-1);
        int rem = i / DIN;
        int row = rem & (BN-1);
        int t = rem / BN;
        float v = input[(size_t)row*TT*DIN + t*DIN + k];
        __nv_bfloat16 h,l; split_bf16(v, h, l);
        g_Xhi[i]=h; g_Xlo[i]=l;
    }
}
__global__ void copyh(const float* __restrict__ hn){
    int i = blockIdx.x*blockDim.x + threadIdx.x;
    if (i < BN*HH){
        float v = hn[i];
        g_hf[i] = v;
        __nv_bfloat16 h,l; split_bf16(v, h, l);
        g_Ahi[i]=h; g_Alo[i]=l;   // buffer 0
    }
}

// ---------------- mma.sync GRU step ----------------
// grid (16 n-tiles, 8 m-tiles), 256 threads. CTA tile: M=128 x 32 cols/gate.
// SMEM per buffer: A hi/lo 128x32 bf16 (stride 80B) + B hi/lo 96x32 bf16.
static constexpr int APL = 128*80;        // 10240 bytes per A plane
static constexpr int BPL = 96*80;         // 7680 bytes per B plane
static constexpr int OB  = 2*APL;         // 20480
static constexpr int BUFB = 2*APL + 2*BPL;  // 35840
static constexpr int SMEM_STEP = 2*BUFB;    // 71680

__global__ void __launch_bounds__(256, 1)
step_mma(const float* __restrict__ bhh, int t)
{
    extern __shared__ char smem[];
    const u32 sb = smem_u32(smem);
    const int tid = threadIdx.x;
    const int lane = tid & 31, wid = tid >> 5;
    const int wm = wid & 3;         // m quarter (32 rows)
    const int wn = wid >> 2;        // n half (16 cols per gate)
    const int bn0 = blockIdx.x * 32;
    const int bm0 = blockIdx.y * 128;
    const int src = t & 1, dst = src ^ 1;

    const __nv_bfloat16* aHiG = g_Ahi + (size_t)src*BN*HH;
    const __nv_bfloat16* aLoG = g_Alo + (size_t)src*BN*HH;
    const __nv_bfloat16* xHiG = g_Xhi + (size_t)t*BN*DIN;
    const __nv_bfloat16* xLoG = g_Xlo + (size_t)t*BN*DIN;

    // ---- staging: 1792 x 16B cp.async per chunk (7 per thread) ----
    auto stage = [&](int c){
        const int buf = c & 1;
        const u32 sbase = sb + buf*BUFB;
        #pragma unroll
        for (int rep = 0; rep < 7; ++rep){
            int idx = rep*256 + tid;
            const __nv_bfloat16* g;
            u32 so;
            if (idx < 1024){                       // A planes
                int plane = idx >> 9;              // 0=hi,1=lo
                int row = (idx >> 2) & 127;
                int seg = idx & 3;
                if (c < 16){
                    const __nv_bfloat16* base = plane ? aLoG : aHiG;
                    g = base + (size_t)(bm0+row)*HH + c*32 + seg*8;
                } else {
                    const __nv_bfloat16* base = plane ? xLoG : xHiG;
                    g = base + (size_t)(bm0+row)*DIN + seg*8;
                }
                so = sbase + plane*APL + row*80 + seg*16;
            } else {                               // B planes
                int b = idx - 1024;
                int plane = (b >= 384) ? 1 : 0;
                int w = b - plane*384;
                int row = w >> 2;                  // 0..95
                int seg = w & 3;
                int gRow = (row >> 5)*HH + bn0 + (row & 31);
                if (c < 16) g = (plane ? g_Bhlo : g_Bhhi) + (size_t)gRow*HH + c*32 + seg*8;
                else        g = (plane ? g_Bxlo : g_Bxhi) + (size_t)gRow*DIN + seg*8;
                so = sbase + OB + plane*BPL + row*80 + seg*16;
            }
            cp16(so, g);
        }
        CP_COMMIT();
    };

    float acc[4][2][2][4];            // [r,z,nh,nx][mi][ni][frag]
    #pragma unroll
    for (int a = 0; a < 4; ++a)
        #pragma unroll
        for (int m = 0; m < 2; ++m)
            #pragma unroll
            for (int n = 0; n < 2; ++n)
                #pragma unroll
                for (int q = 0; q < 4; ++q) acc[a][m][n][q] = 0.f;

#define COMPUTE(BUF, XCHUNK)                                                  \
    {   const u32 sA = sb + (BUF)*BUFB;                                       \
        const u32 sB = sA + OB;                                               \
        _Pragma("unroll")                                                     \
        for (int kk = 0; kk < 2; ++kk){                                       \
            u32 aF[2][2][4];                                                  \
            _Pragma("unroll")                                                 \
            for (int mi = 0; mi < 2; ++mi){                                   \
                u32 rowa = wm*32 + mi*16 + ((lane>>3)&1)*8 + (lane&7);        \
                u32 off = rowa*80 + kk*32 + (lane>>4)*16;                     \
                ldm_x4(aF[0][mi], sA + off);                                  \
                ldm_x4(aF[1][mi], sA + APL + off);                            \
            }                                                                 \
            _Pragma("unroll")                                                 \
            for (int gate = 0; gate < 3; ++gate){                             \
                u32 bF[2][2][2];                                              \
                _Pragma("unroll")                                             \
                for (int ni = 0; ni < 2; ++ni){                               \
                    u32 rowb = gate*32 + wn*16 + ni*8 + (lane&7);             \
                    u32 off = rowb*80 + kk*32 + ((lane>>3)&1)*16;             \
                    ldm_x2(bF[0][ni], sB + off);                              \
                    ldm_x2(bF[1][ni], sB + BPL + off);                        \
                }                                                             \
                const int g2 = ((XCHUNK) && gate == 2) ? 3 : gate;            \
                _Pragma("unroll")                                             \
                for (int mi = 0; mi < 2; ++mi)                                \
                    _Pragma("unroll")                                         \
                    for (int ni = 0; ni < 2; ++ni){                           \
                        mma_bf16(acc[g2][mi][ni], aF[0][mi], bF[0][ni]);      \
                        mma_bf16(acc[g2][mi][ni], aF[1][mi], bF[0][ni]);      \
                        mma_bf16(acc[g2][mi][ni], aF[0][mi], bF[1][ni]);      \
                    }                                                         \
            }                                                                 \
        }                                                                     \
    }

    stage(0);
    #pragma unroll 1
    for (int c = 0; c < 16; ++c){
        stage(c + 1);
        CP_WAIT(1);
        __syncthreads();
        COMPUTE(c & 1, 0)
        __syncthreads();
    }
    CP_WAIT(0);
    __syncthreads();
    COMPUTE(0, 1)          // chunk 16 (x) lives in buffer 0 (16&1==0)
#undef COMPUTE

    // ---- epilogue: gates + h update ----
    float bsr[2][2], bsz[2][2], bgn_[2][2], bhn_[2][2];
    #pragma unroll
    for (int ni = 0; ni < 2; ++ni)
        #pragma unroll
        for (int j = 0; j < 2; ++j){
            int col = bn0 + wn*16 + ni*8 + 2*(lane&3) + j;
            bsr[ni][j]  = g_bg[col] + bhh[col];
            bsz[ni][j]  = g_bg[HH + col] + bhh[HH + col];
            bgn_[ni][j] = g_bg[2*HH + col];
            bhn_[ni][j] = bhh[2*HH + col];
        }

    __nv_bfloat16* dHi = g_Ahi + (size_t)dst*BN*HH;
    __nv_bfloat16* dLo = g_Alo + (size_t)dst*BN*HH;
    #pragma unroll
    for (int mi = 0; mi < 2; ++mi)
        #pragma unroll
        for (int ph = 0; ph < 2; ++ph){
            int r = bm0 + wm*32 + mi*16 + (lane>>2) + ph*8;
            #pragma unroll
            for (int ni = 0; ni < 2; ++ni){
                int colb = bn0 + wn*16 + ni*8 + 2*(lane&3);
                float2 ho = *(const float2*)(g_hf + (size_t)r*HH + colb);
                float hnew[2];
                #pragma unroll
                for (int j = 0; j < 2; ++j){
                    int q = ph*2 + j;
                    float r_ = sigm(acc[0][mi][ni][q] + bsr[ni][j]);
                    float z_ = sigm(acc[1][mi][ni][q] + bsz[ni][j]);
                    float n_ = tanh_(acc[3][mi][ni][q] + bgn_[ni][j]
                                     + r_*(acc[2][mi][ni][q] + bhn_[ni][j]));
                    float hv = j ? ho.y : ho.x;
                    hnew[j] = n_ + z_*(hv - n_);
                }
                *(float2*)(g_hf + (size_t)r*HH + colb) = make_float2(hnew[0], hnew[1]);
                __nv_bfloat16 h0,l0,h1,l1;
                split_bf16(hnew[0], h0, l0);
                split_bf16(hnew[1], h1, l1);
                *(__nv_bfloat162*)(dHi + (size_t)r*HH + colb) = __nv_bfloat162(h0, h1);
                *(__nv_bfloat162*)(dLo + (size_t)r*HH + colb) = __nv_bfloat162(l0, l1);
            }
        }
}

// ---------------- out2 = relu(relu(h) @ W3^T + b3) ----------------
__global__ void __launch_bounds__(256)
f1_kernel(const float* __restrict__ W3, const float* __restrict__ b3)
{
    __shared__ float As[16][68];
    __shared__ float Bs[16][68];
    const float* h = g_hf;
    int tid = threadIdx.x;
    int tx = tid & 15, ty = tid >> 4;
    int m0 = ty*4, n0 = tx*4;
    int bm0 = blockIdx.y*64, bn0 = blockIdx.x*64;
    int arow = tid >> 2, akq = (tid & 3) << 2;
    float acc[4][4] = {};
    for (int cc = 0; cc < HH/16; ++cc){
        int k0 = cc*16;
        float4 va = *(const float4*)(h  + (size_t)(bm0+arow)*HH + k0 + akq);
        va.x = fmaxf(va.x, 0.f); va.y = fmaxf(va.y, 0.f);
        va.z = fmaxf(va.z, 0.f); va.w = fmaxf(va.w, 0.f);
        float4 vb = *(const float4*)(W3 + (size_t)(bn0+arow)*HH + k0 + akq);
        __syncthreads();
        As[akq+0][arow] = va.x; As[akq+1][arow] = va.y;
        As[akq+2][arow] = va.z; As[akq+3][arow] = va.w;
        Bs[akq+0][arow] = vb.x; Bs[akq+1][arow] = vb.y;
        Bs[akq+2][arow] = vb.z; Bs[akq+3][arow] = vb.w;
        __syncthreads();
        #pragma unroll
        for (int k = 0; k < 16; ++k){
            float a[4], b[4];
            #pragma unroll
            for (int j = 0; j < 4; ++j){ a[j] = As[k][m0+j]; b[j] = Bs[k][n0+j]; }
            #pragma unroll
            for (int i = 0; i < 4; ++i)
                #pragma unroll
                for (int j = 0; j < 4; ++j)
                    acc[i][j] += a[i]*b[j];
        }
    }
    #pragma unroll
    for (int i = 0; i < 4; ++i){
        int row = bm0 + m0 + i;
        float4 o;
        o.x = fmaxf(acc[i][0] + b3[bn0+n0+0], 0.f);
        o.y = fmaxf(acc[i][1] + b3[bn0+n0+1], 0.f);
        o.z = fmaxf(acc[i][2] + b3[bn0+n0+2], 0.f);
        o.w = fmaxf(acc[i][3] + b3[bn0+n0+3], 0.f);
        *(float4*)(&g_out2[(size_t)row*DD2 + bn0 + n0]) = o;
    }
}

// ---------------- per-cultivar head + output write ----------------
__global__ void f2_kernel(const int* __restrict__ cult,
                          const float* __restrict__ Wh, const float* __restrict__ bh,
                          float* __restrict__ out)
{
    int b = blockIdx.x;
    int tid = threadIdx.x;
    __shared__ float s[DD2];
    s[tid] = g_out2[(size_t)b*DD2 + tid];
    __syncthreads();
    int c = cult[b];
    int o = tid >> 4, lane = tid & 15;
    const float* w = Wh + ((size_t)c*DOUT + o)*DD2;
    float acc = 0.f;
    for (int k = lane; k < DD2; k += 16) acc += s[k]*w[k];
    #pragma unroll
    for (int off = 8; off; off >>= 1) acc += __shfl_down_sync(0xffffffffu, acc, off, 16);
    if (lane == 0) out[(size_t)b*DOUT + o] = acc + bh[c*DOUT + o];
    for (int i = tid; i < HH; i += 256)
        out[(size_t)BN*DOUT + (size_t)b*HH + i] = g_hf[(size_t)b*HH + i];
}

// ---------------- launcher ----------------
extern "C" void kernel_launch(void* const* d_in, const int* in_sizes, int n_in,
                              void* d_out, int out_size)
{
    const float* input = (const float*)d_in[0];
    const float* hn    = (const float*)d_in[1];
    const int*   cult  = (const int*)d_in[2];
    const float* W1    = (const float*)d_in[3];
    const float* b1    = (const float*)d_in[4];
    const float* W2    = (const float*)d_in[5];
    const float* b2    = (const float*)d_in[6];
    const float* W_ih  = (const float*)d_in[7];
    const float* W_hh  = (const float*)d_in[8];
    const float* b_ih  = (const float*)d_in[9];
    const float* b_hh  = (const float*)d_in[10];
    const float* W3    = (const float*)d_in[11];
    const float* b3    = (const float*)d_in[12];
    const float* Wh    = (const float*)d_in[13];
    const float* bh    = (const float*)d_in[14];
    float* out = (float*)d_out;

    cudaFuncSetAttribute(step_mma, cudaFuncAttributeMaxDynamicSharedMemorySize, SMEM_STEP);

    fold1<<<HH, 32>>>(W2, W1, b1, b2);
    fold2<<<GG, 32>>>(W_ih, b_ih);
    packBh<<<(GG*HH + 255)/256, 256>>>(W_hh);
    packBx<<<(GG*DIN + 255)/256, 256>>>();
    packX<<<(TT*BN*DIN + 255)/256, 256>>>(input);
    copyh<<<(BN*HH + 255)/256, 256>>>(hn);

    for (int t = 0; t < TT; ++t)
        step_mma<<<dim3(16, 8), 256, SMEM_STEP>>>(b_hh, t);

    f1_kernel<<<dim3(DD2/64, BN/64), 256>>>(W3, b3);
    f2_kernel<<<BN, 256>>>(cult, Wh, bh, out);
}

// round 9
// speedup vs baseline: 1.0005x; 1.0005x over previous
#include <cuda_runtime.h>
#include <cuda_bf16.h>
#include <cstdint>

#define BN 1024
#define TT 128
#define DIN 32
#define HH 512
#define DD2 256
#define DOUT 16
#define GG 1536

typedef unsigned int u32;
typedef unsigned long long u64;

// ---------------- device globals (static scratch; no allocation) ----------------
__device__ float g_Weff[HH*DIN];
__device__ float g_beff[HH];
__device__ float g_Wg[GG*DIN];     // folded input weight (1536 x 32)
__device__ float g_bg[GG];         // folded input bias
__device__ float g_hf[BN*HH];      // fp32 hidden state
__device__ float g_out2[BN*DD2];
__device__ __align__(16) __nv_bfloat16 g_Ahi[2*BN*HH];   // h planes, ping-pong
__device__ __align__(16) __nv_bfloat16 g_Alo[2*BN*HH];
__device__ __align__(16) __nv_bfloat16 g_Xhi[TT*BN*DIN]; // input planes, t-major
__device__ __align__(16) __nv_bfloat16 g_Xlo[TT*BN*DIN];
__device__ __align__(16) __nv_bfloat16 g_Bhhi[GG*HH];    // W_hh planes (row-major g,k)
__device__ __align__(16) __nv_bfloat16 g_Bhlo[GG*HH];
__device__ __align__(16) __nv_bfloat16 g_Bxhi[GG*DIN];   // Wg planes
__device__ __align__(16) __nv_bfloat16 g_Bxlo[GG*DIN];

// ---------------- helpers ----------------
__device__ __forceinline__ float sigm(float x){
    float e; asm("ex2.approx.f32 %0, %1;" : "=f"(e) : "f"(-1.4426950408889634f*x));
    float r; asm("rcp.approx.f32 %0, %1;" : "=f"(r) : "f"(1.0f + e));
    return r;
}
__device__ __forceinline__ float tanh_(float x){ return 2.0f*sigm(2.0f*x) - 1.0f; }

__device__ __forceinline__ u32 smem_u32(const void* p){
    u32 a; asm("{ .reg .u64 t; cvta.to.shared.u64 t, %1; cvt.u32.u64 %0, t; }" : "=r"(a) : "l"(p));
    return a;
}
__device__ __forceinline__ void mma_bf16(float* d, const u32* a, const u32* b){
    asm volatile("mma.sync.aligned.m16n8k16.row.col.f32.bf16.bf16.f32 "
        "{%0,%1,%2,%3}, {%4,%5,%6,%7}, {%8,%9}, {%0,%1,%2,%3};"
        : "+f"(d[0]), "+f"(d[1]), "+f"(d[2]), "+f"(d[3])
        : "r"(a[0]), "r"(a[1]), "r"(a[2]), "r"(a[3]), "r"(b[0]), "r"(b[1]));
}
__device__ __forceinline__ void ldm_x4(u32* r, u32 addr){
    asm volatile("ldmatrix.sync.aligned.m8n8.x4.shared.b16 {%0,%1,%2,%3}, [%4];"
        : "=r"(r[0]),"=r"(r[1]),"=r"(r[2]),"=r"(r[3]) : "r"(addr));
}
__device__ __forceinline__ void ldm_x2(u32* r, u32 addr){
    asm volatile("ldmatrix.sync.aligned.m8n8.x2.shared.b16 {%0,%1}, [%2];"
        : "=r"(r[0]),"=r"(r[1]) : "r"(addr));
}
__device__ __forceinline__ void cp16(u32 saddr, const void* g){
    asm volatile("cp.async.cg.shared.global [%0], [%1], 16;" :: "r"(saddr), "l"(g));
}
#define CP_COMMIT() asm volatile("cp.async.commit_group;" ::: "memory")
#define CP_WAIT(n)  asm volatile("cp.async.wait_group %0;" :: "n"(n) : "memory")

__device__ __forceinline__ void split_bf16(float v, __nv_bfloat16 &hi, __nv_bfloat16 &lo){
    hi = __float2bfloat16(v);
    lo = __float2bfloat16(v - __bfloat162float(hi));
}

// ---------------- weight folding ----------------
__global__ void fold1(const float* __restrict__ W2, const float* __restrict__ W1,
                      const float* __restrict__ b1, const float* __restrict__ b2)
{
    int i = blockIdx.x, k = threadIdx.x;
    float acc = 0.f, pb = 0.f;
    for (int j = 0; j < DD2; ++j) acc += W2[i*DD2 + j] * W1[j*DIN + k];
    for (int j = k; j < DD2; j += 32) pb += W2[i*DD2 + j]*b1[j];
    g_Weff[i*DIN + k] = acc;
    #pragma unroll
    for (int o = 16; o; o >>= 1) pb += __shfl_down_sync(0xffffffffu, pb, o);
    if (k == 0) g_beff[i] = pb + b2[i];
}
__global__ void fold2(const float* __restrict__ Wih, const float* __restrict__ bih)
{
    int g = blockIdx.x, k = threadIdx.x;
    float acc = 0.f, pb = 0.f;
    for (int i = 0; i < HH; ++i) acc += Wih[g*HH + i] * g_Weff[i*DIN + k];
    for (int i = k; i < HH; i += 32) pb += Wih[g*HH + i]*g_beff[i];
    g_Wg[g*DIN + k] = acc;
    #pragma unroll
    for (int o = 16; o; o >>= 1) pb += __shfl_down_sync(0xffffffffu, pb, o);
    if (k == 0) g_bg[g] = pb + bih[g];
}
__global__ void packBh(const float* __restrict__ Whh){
    int i = blockIdx.x*blockDim.x + threadIdx.x;
    if (i < GG*HH){ __nv_bfloat16 h,l; split_bf16(Whh[i], h, l); g_Bhhi[i]=h; g_Bhlo[i]=l; }
}
__global__ void packBx(){
    int i = blockIdx.x*blockDim.x + threadIdx.x;
    if (i < GG*DIN){ __nv_bfloat16 h,l; split_bf16(g_Wg[i], h, l); g_Bxhi[i]=h; g_Bxlo[i]=l; }
}
__global__ void packX(const float* __restrict__ input){
    int i = blockIdx.x*blockDim.x + threadIdx.x;      // t-major index
    if (i < TT*BN*DIN){
        int k = i & (DIN-1);
        int rem = i / DIN;
        int row = rem & (BN-1);
        int t = rem / BN;
        float v = input[(size_t)row*TT*DIN + t*DIN + k];
        __nv_bfloat16 h,l; split_bf16(v, h, l);
        g_Xhi[i]=h; g_Xlo[i]=l;
    }
}
__global__ void copyh(const float* __restrict__ hn){
    int i = blockIdx.x*blockDim.x + threadIdx.x;
    if (i < BN*HH){
        float v = hn[i];
        g_hf[i] = v;
        __nv_bfloat16 h,l; split_bf16(v, h, l);
        g_Ahi[i]=h; g_Alo[i]=l;   // buffer 0
    }
}

// ---------------- mma.sync GRU step ----------------
// grid (16 n-tiles, 8 m-tiles), 256 threads. CTA tile: M=128 x 32 cols/gate.
// SMEM per buffer: A hi/lo 128x32 bf16 (stride 80B) + B hi/lo 96x32 bf16.
static constexpr int APL = 128*80;        // 10240 bytes per A plane
static constexpr int BPL = 96*80;         // 7680 bytes per B plane
static constexpr int OB  = 2*APL;         // 20480
static constexpr int BUFB = 2*APL + 2*BPL;  // 35840
static constexpr int SMEM_STEP = 2*BUFB;    // 71680

__global__ void __launch_bounds__(256, 1)
step_mma(const float* __restrict__ bhh, int t)
{
    extern __shared__ char smem[];
    const u32 sb = smem_u32(smem);
    const int tid = threadIdx.x;
    const int lane = tid & 31, wid = tid >> 5;
    const int wm = wid & 3;         // m quarter (32 rows)
    const int wn = wid >> 2;        // n half (16 cols per gate)
    const int bn0 = blockIdx.x * 32;
    const int bm0 = blockIdx.y * 128;
    const int src = t & 1, dst = src ^ 1;

    const __nv_bfloat16* aHiG = g_Ahi + (size_t)src*BN*HH;
    const __nv_bfloat16* aLoG = g_Alo + (size_t)src*BN*HH;
    const __nv_bfloat16* xHiG = g_Xhi + (size_t)t*BN*DIN;
    const __nv_bfloat16* xLoG = g_Xlo + (size_t)t*BN*DIN;

    // ---- staging: 1792 x 16B cp.async per chunk (7 per thread) ----
    auto stage = [&](int c){
        const int buf = c & 1;
        const u32 sbase = sb + buf*BUFB;
        #pragma unroll
        for (int rep = 0; rep < 7; ++rep){
            int idx = rep*256 + tid;
            const __nv_bfloat16* g;
            u32 so;
            if (idx < 1024){                       // A planes
                int plane = idx >> 9;              // 0=hi,1=lo
                int row = (idx >> 2) & 127;
                int seg = idx & 3;
                if (c < 16){
                    const __nv_bfloat16* base = plane ? aLoG : aHiG;
                    g = base + (size_t)(bm0+row)*HH + c*32 + seg*8;
                } else {
                    const __nv_bfloat16* base = plane ? xLoG : xHiG;
                    g = base + (size_t)(bm0+row)*DIN + seg*8;
                }
                so = sbase + plane*APL + row*80 + seg*16;
            } else {                               // B planes
                int b = idx - 1024;
                int plane = (b >= 384) ? 1 : 0;
                int w = b - plane*384;
                int row = w >> 2;                  // 0..95
                int seg = w & 3;
                int gRow = (row >> 5)*HH + bn0 + (row & 31);
                if (c < 16) g = (plane ? g_Bhlo : g_Bhhi) + (size_t)gRow*HH + c*32 + seg*8;
                else        g = (plane ? g_Bxlo : g_Bxhi) + (size_t)gRow*DIN + seg*8;
                so = sbase + OB + plane*BPL + row*80 + seg*16;
            }
            cp16(so, g);
        }
        CP_COMMIT();
    };

    float acc[4][2][2][4];            // [r,z,nh,nx][mi][ni][frag]
    #pragma unroll
    for (int a = 0; a < 4; ++a)
        #pragma unroll
        for (int m = 0; m < 2; ++m)
            #pragma unroll
            for (int n = 0; n < 2; ++n)
                #pragma unroll
                for (int q = 0; q < 4; ++q) acc[a][m][n][q] = 0.f;

#define COMPUTE(BUF, XCHUNK)                                                  \
    {   const u32 sA = sb + (BUF)*BUFB;                                       \
        const u32 sB = sA + OB;                                               \
        _Pragma("unroll")                                                     \
        for (int kk = 0; kk < 2; ++kk){                                       \
            u32 aF[2][2][4];                                                  \
            _Pragma("unroll")                                                 \
            for (int mi = 0; mi < 2; ++mi){                                   \
                u32 rowa = wm*32 + mi*16 + ((lane>>3)&1)*8 + (lane&7);        \
                u32 off = rowa*80 + kk*32 + (lane>>4)*16;                     \
                ldm_x4(aF[0][mi], sA + off);                                  \
                ldm_x4(aF[1][mi], sA + APL + off);                            \
            }                                                                 \
            _Pragma("unroll")                                                 \
            for (int gate = 0; gate < 3; ++gate){                             \
                u32 bF[2][2][2];                                              \
                _Pragma("unroll")                                             \
                for (int ni = 0; ni < 2; ++ni){                               \
                    u32 rowb = gate*32 + wn*16 + ni*8 + (lane&7);             \
                    u32 off = rowb*80 + kk*32 + ((lane>>3)&1)*16;             \
                    ldm_x2(bF[0][ni], sB + off);                              \
                    ldm_x2(bF[1][ni], sB + BPL + off);                        \
                }                                                             \
                const int g2 = ((XCHUNK) && gate == 2) ? 3 : gate;            \
                _Pragma("unroll")                                             \
                for (int mi = 0; mi < 2; ++mi)                                \
                    _Pragma("unroll")                                         \
                    for (int ni = 0; ni < 2; ++ni){                           \
                        mma_bf16(acc[g2][mi][ni], aF[0][mi], bF[0][ni]);      \
                        mma_bf16(acc[g2][mi][ni], aF[1][mi], bF[0][ni]);      \
                        mma_bf16(acc[g2][mi][ni], aF[0][mi], bF[1][ni]);      \
                    }                                                         \
            }                                                                 \
        }                                                                     \
    }

    stage(0);
    #pragma unroll 1
    for (int c = 0; c < 16; ++c){
        stage(c + 1);
        CP_WAIT(1);
        __syncthreads();
        COMPUTE(c & 1, 0)
        __syncthreads();
    }
    CP_WAIT(0);
    __syncthreads();
    COMPUTE(0, 1)          // chunk 16 (x) lives in buffer 0 (16&1==0)
#undef COMPUTE

    // ---- epilogue: gates + h update ----
    float bsr[2][2], bsz[2][2], bgn_[2][2], bhn_[2][2];
    #pragma unroll
    for (int ni = 0; ni < 2; ++ni)
        #pragma unroll
        for (int j = 0; j < 2; ++j){
            int col = bn0 + wn*16 + ni*8 + 2*(lane&3) + j;
            bsr[ni][j]  = g_bg[col] + bhh[col];
            bsz[ni][j]  = g_bg[HH + col] + bhh[HH + col];
            bgn_[ni][j] = g_bg[2*HH + col];
            bhn_[ni][j] = bhh[2*HH + col];
        }

    __nv_bfloat16* dHi = g_Ahi + (size_t)dst*BN*HH;
    __nv_bfloat16* dLo = g_Alo + (size_t)dst*BN*HH;
    #pragma unroll
    for (int mi = 0; mi < 2; ++mi)
        #pragma unroll
        for (int ph = 0; ph < 2; ++ph){
            int r = bm0 + wm*32 + mi*16 + (lane>>2) + ph*8;
            #pragma unroll
            for (int ni = 0; ni < 2; ++ni){
                int colb = bn0 + wn*16 + ni*8 + 2*(lane&3);
                float2 ho = *(const float2*)(g_hf + (size_t)r*HH + colb);
                float hnew[2];
                #pragma unroll
                for (int j = 0; j < 2; ++j){
                    int q = ph*2 + j;
                    float r_ = sigm(acc[0][mi][ni][q] + bsr[ni][j]);
                    float z_ = sigm(acc[1][mi][ni][q] + bsz[ni][j]);
                    float n_ = tanh_(acc[3][mi][ni][q] + bgn_[ni][j]
                                     + r_*(acc[2][mi][ni][q] + bhn_[ni][j]));
                    float hv = j ? ho.y : ho.x;
                    hnew[j] = n_ + z_*(hv - n_);
                }
                *(float2*)(g_hf + (size_t)r*HH + colb) = make_float2(hnew[0], hnew[1]);
                __nv_bfloat16 h0,l0,h1,l1;
                split_bf16(hnew[0], h0, l0);
                split_bf16(hnew[1], h1, l1);
                *(__nv_bfloat162*)(dHi + (size_t)r*HH + colb) = __nv_bfloat162(h0, h1);
                *(__nv_bfloat162*)(dLo + (size_t)r*HH + colb) = __nv_bfloat162(l0, l1);
            }
        }
}

// ---------------- out2 = relu(relu(h) @ W3^T + b3) ----------------
__global__ void __launch_bounds__(256)
f1_kernel(const float* __restrict__ W3, const float* __restrict__ b3)
{
    __shared__ float As[16][68];
    __shared__ float Bs[16][68];
    const float* h = g_hf;
    int tid = threadIdx.x;
    int tx = tid & 15, ty = tid >> 4;
    int m0 = ty*4, n0 = tx*4;
    int bm0 = blockIdx.y*64, bn0 = blockIdx.x*64;
    int arow = tid >> 2, akq = (tid & 3) << 2;
    float acc[4][4] = {};
    for (int cc = 0; cc < HH/16; ++cc){
        int k0 = cc*16;
        float4 va = *(const float4*)(h  + (size_t)(bm0+arow)*HH + k0 + akq);
        va.x = fmaxf(va.x, 0.f); va.y = fmaxf(va.y, 0.f);
        va.z = fmaxf(va.z, 0.f); va.w = fmaxf(va.w, 0.f);
        float4 vb = *(const float4*)(W3 + (size_t)(bn0+arow)*HH + k0 + akq);
        __syncthreads();
        As[akq+0][arow] = va.x; As[akq+1][arow] = va.y;
        As[akq+2][arow] = va.z; As[akq+3][arow] = va.w;
        Bs[akq+0][arow] = vb.x; Bs[akq+1][arow] = vb.y;
        Bs[akq+2][arow] = vb.z; Bs[akq+3][arow] = vb.w;
        __syncthreads();
        #pragma unroll
        for (int k = 0; k < 16; ++k){
            float a[4], b[4];
            #pragma unroll
            for (int j = 0; j < 4; ++j){ a[j] = As[k][m0+j]; b[j] = Bs[k][n0+j]; }
            #pragma unroll
            for (int i = 0; i < 4; ++i)
                #pragma unroll
                for (int j = 0; j < 4; ++j)
                    acc[i][j] += a[i]*b[j];
        }
    }
    #pragma unroll
    for (int i = 0; i < 4; ++i){
        int row = bm0 + m0 + i;
        float4 o;
        o.x = fmaxf(acc[i][0] + b3[bn0+n0+0], 0.f);
        o.y = fmaxf(acc[i][1] + b3[bn0+n0+1], 0.f);
        o.z = fmaxf(acc[i][2] + b3[bn0+n0+2], 0.f);
        o.w = fmaxf(acc[i][3] + b3[bn0+n0+3], 0.f);
        *(float4*)(&g_out2[(size_t)row*DD2 + bn0 + n0]) = o;
    }
}

// ---------------- per-cultivar head + output write ----------------
__global__ void f2_kernel(const int* __restrict__ cult,
                          const float* __restrict__ Wh, const float* __restrict__ bh,
                          float* __restrict__ out)
{
    int b = blockIdx.x;
    int tid = threadIdx.x;
    __shared__ float s[DD2];
    s[tid] = g_out2[(size_t)b*DD2 + tid];
    __syncthreads();
    int c = cult[b];
    int o = tid >> 4, lane = tid & 15;
    const float* w = Wh + ((size_t)c*DOUT + o)*DD2;
    float acc = 0.f;
    for (int k = lane; k < DD2; k += 16) acc += s[k]*w[k];
    #pragma unroll
    for (int off = 8; off; off >>= 1) acc += __shfl_down_sync(0xffffffffu, acc, off, 16);
    if (lane == 0) out[(size_t)b*DOUT + o] = acc + bh[c*DOUT + o];
    for (int i = tid; i < HH; i += 256)
        out[(size_t)BN*DOUT + (size_t)b*HH + i] = g_hf[(size_t)b*HH + i];
}

// ---------------- launcher ----------------
extern "C" void kernel_launch(void* const* d_in, const int* in_sizes, int n_in,
                              void* d_out, int out_size)
{
    const float* input = (const float*)d_in[0];
    const float* hn    = (const float*)d_in[1];
    const int*   cult  = (const int*)d_in[2];
    const float* W1    = (const float*)d_in[3];
    const float* b1    = (const float*)d_in[4];
    const float* W2    = (const float*)d_in[5];
    const float* b2    = (const float*)d_in[6];
    const float* W_ih  = (const float*)d_in[7];
    const float* W_hh  = (const float*)d_in[8];
    const float* b_ih  = (const float*)d_in[9];
    const float* b_hh  = (const float*)d_in[10];
    const float* W3    = (const float*)d_in[11];
    const float* b3    = (const float*)d_in[12];
    const float* Wh    = (const float*)d_in[13];
    const float* bh    = (const float*)d_in[14];
    float* out = (float*)d_out;

    cudaFuncSetAttribute(step_mma, cudaFuncAttributeMaxDynamicSharedMemorySize, SMEM_STEP);

    fold1<<<HH, 32>>>(W2, W1, b1, b2);
    fold2<<<GG, 32>>>(W_ih, b_ih);
    packBh<<<(GG*HH + 255)/256, 256>>>(W_hh);
    packBx<<<(GG*DIN + 255)/256, 256>>>();
    packX<<<(TT*BN*DIN + 255)/256, 256>>>(input);
    copyh<<<(BN*HH + 255)/256, 256>>>(hn);

    for (int t = 0; t < TT; ++t)
        step_mma<<<dim3(16, 8), 256, SMEM_STEP>>>(b_hh, t);

    f1_kernel<<<dim3(DD2/64, BN/64), 256>>>(W3, b3);
    f2_kernel<<<BN, 256>>>(cult, Wh, bh, out);
}

// round 10
// speedup vs baseline: 1.1445x; 1.1440x over previous
#include <cuda_runtime.h>
#include <cuda_bf16.h>
#include <cstdint>

#define BN 1024
#define TT 128
#define DIN 32
#define HH 512
#define DD2 256
#define DOUT 16
#define GG 1536

typedef unsigned int u32;
typedef unsigned long long u64;

// ---------------- device globals (static scratch; no allocation) ----------------
__device__ float g_Weff[HH*DIN];
__device__ float g_beff[HH];
__device__ float g_Wg[GG*DIN];     // folded input weight (1536 x 32)
__device__ float g_bg[GG];         // folded input bias
__device__ float g_hf[BN*HH];      // fp32 hidden state (final only)
__device__ float g_out2[BN*DD2];
__device__ u32   g_bar;            // global step barrier counter
__device__ __align__(16) __nv_bfloat16 g_Ahi[2*BN*HH];   // h planes, ping-pong
__device__ __align__(16) __nv_bfloat16 g_Alo[2*BN*HH];
__device__ __align__(16) __nv_bfloat16 g_Xhi[TT*BN*DIN]; // input planes, t-major
__device__ __align__(16) __nv_bfloat16 g_Xlo[TT*BN*DIN];
__device__ __align__(16) __nv_bfloat16 g_Bhhi[GG*HH];    // W_hh planes (row-major g,k)
__device__ __align__(16) __nv_bfloat16 g_Bhlo[GG*HH];
__device__ __align__(16) __nv_bfloat16 g_Bxhi[GG*DIN];   // Wg planes
__device__ __align__(16) __nv_bfloat16 g_Bxlo[GG*DIN];

// ---------------- helpers ----------------
__device__ __forceinline__ float sigm(float x){
    float e; asm("ex2.approx.f32 %0, %1;" : "=f"(e) : "f"(-1.4426950408889634f*x));
    float r; asm("rcp.approx.f32 %0, %1;" : "=f"(r) : "f"(1.0f + e));
    return r;
}
__device__ __forceinline__ float tanh_(float x){ return 2.0f*sigm(2.0f*x) - 1.0f; }

__device__ __forceinline__ u32 smem_u32(const void* p){
    u32 a; asm("{ .reg .u64 t; cvta.to.shared.u64 t, %1; cvt.u32.u64 %0, t; }" : "=r"(a) : "l"(p));
    return a;
}
__device__ __forceinline__ void mma_bf16(float* d, const u32* a, const u32* b){
    asm volatile("mma.sync.aligned.m16n8k16.row.col.f32.bf16.bf16.f32 "
        "{%0,%1,%2,%3}, {%4,%5,%6,%7}, {%8,%9}, {%0,%1,%2,%3};"
        : "+f"(d[0]), "+f"(d[1]), "+f"(d[2]), "+f"(d[3])
        : "r"(a[0]), "r"(a[1]), "r"(a[2]), "r"(a[3]), "r"(b[0]), "r"(b[1]));
}
__device__ __forceinline__ void ldm_x4(u32* r, u32 addr){
    asm volatile("ldmatrix.sync.aligned.m8n8.x4.shared.b16 {%0,%1,%2,%3}, [%4];"
        : "=r"(r[0]),"=r"(r[1]),"=r"(r[2]),"=r"(r[3]) : "r"(addr));
}
__device__ __forceinline__ void ldm_x2(u32* r, u32 addr){
    asm volatile("ldmatrix.sync.aligned.m8n8.x2.shared.b16 {%0,%1}, [%2];"
        : "=r"(r[0]),"=r"(r[1]) : "r"(addr));
}
__device__ __forceinline__ void cp16(u32 saddr, const void* g){
    asm volatile("cp.async.cg.shared.global [%0], [%1], 16;" :: "r"(saddr), "l"(g));
}
#define CP_COMMIT() asm volatile("cp.async.commit_group;" ::: "memory")
#define CP_WAIT(n)  asm volatile("cp.async.wait_group %0;" :: "n"(n) : "memory")

__device__ __forceinline__ void split_bf16(float v, __nv_bfloat16 &hi, __nv_bfloat16 &lo){
    hi = __float2bfloat16(v);
    lo = __float2bfloat16(v - __bfloat162float(hi));
}

// ---------------- weight folding ----------------
__global__ void fold1(const float* __restrict__ W2, const float* __restrict__ W1,
                      const float* __restrict__ b1, const float* __restrict__ b2)
{
    int i = blockIdx.x, k = threadIdx.x;
    float acc = 0.f, pb = 0.f;
    for (int j = 0; j < DD2; ++j) acc += W2[i*DD2 + j] * W1[j*DIN + k];
    for (int j = k; j < DD2; j += 32) pb += W2[i*DD2 + j]*b1[j];
    g_Weff[i*DIN + k] = acc;
    #pragma unroll
    for (int o = 16; o; o >>= 1) pb += __shfl_down_sync(0xffffffffu, pb, o);
    if (k == 0) g_beff[i] = pb + b2[i];
}
__global__ void fold2(const float* __restrict__ Wih, const float* __restrict__ bih)
{
    int g = blockIdx.x, k = threadIdx.x;
    float acc = 0.f, pb = 0.f;
    for (int i = 0; i < HH; ++i) acc += Wih[g*HH + i] * g_Weff[i*DIN + k];
    for (int i = k; i < HH; i += 32) pb += Wih[g*HH + i]*g_beff[i];
    g_Wg[g*DIN + k] = acc;
    #pragma unroll
    for (int o = 16; o; o >>= 1) pb += __shfl_down_sync(0xffffffffu, pb, o);
    if (k == 0) g_bg[g] = pb + bih[g];
}
__global__ void packBh(const float* __restrict__ Whh){
    int i = blockIdx.x*blockDim.x + threadIdx.x;
    if (i < GG*HH){ __nv_bfloat16 h,l; split_bf16(Whh[i], h, l); g_Bhhi[i]=h; g_Bhlo[i]=l; }
}
__global__ void packBx(){
    int i = blockIdx.x*blockDim.x + threadIdx.x;
    if (i < GG*DIN){ __nv_bfloat16 h,l; split_bf16(g_Wg[i], h, l); g_Bxhi[i]=h; g_Bxlo[i]=l; }
}
__global__ void packX(const float* __restrict__ input){
    int i = blockIdx.x*blockDim.x + threadIdx.x;      // t-major index
    if (i < TT*BN*DIN){
        int k = i & (DIN-1);
        int rem = i / DIN;
        int row = rem & (BN-1);
        int t = rem / BN;
        float v = input[(size_t)row*TT*DIN + t*DIN + k];
        __nv_bfloat16 h,l; split_bf16(v, h, l);
        g_Xhi[i]=h; g_Xlo[i]=l;
    }
}
__global__ void copyh(const float* __restrict__ hn){
    int i = blockIdx.x*blockDim.x + threadIdx.x;
    if (i == 0) g_bar = 0;                         // reset step barrier each launch
    if (i < BN*HH){
        float v = hn[i];
        g_hf[i] = v;
        __nv_bfloat16 h,l; split_bf16(v, h, l);
        g_Ahi[i]=h; g_Alo[i]=l;   // buffer 0
    }
}

// ---------------- persistent mma.sync GRU (all 128 steps in one kernel) ----------
// grid (16 n-tiles, 8 m-tiles) = 128 CTAs, 256 threads. CTA tile: M=128 x 32/gate.
// 3 smem buffers: A hi/lo 128x32 bf16 (stride 80B) + B hi/lo 96x32 bf16.
static constexpr int APL = 128*80;          // 10240 bytes per A plane
static constexpr int BPL = 96*80;           // 7680 bytes per B plane
static constexpr int OB  = 2*APL;           // 20480
static constexpr int BUFB = 2*APL + 2*BPL;  // 35840
static constexpr int NBUF = 3;
static constexpr int SMEM_STEP = NBUF*BUFB; // 107520

__global__ void __launch_bounds__(256, 1)
gru_persist(const float* __restrict__ bhh)
{
    extern __shared__ char smem[];
    const u32 sb = smem_u32(smem);
    const int tid = threadIdx.x;
    const int lane = tid & 31, wid = tid >> 5;
    const int wm = wid & 3;         // m quarter (32 rows)
    const int wn = wid >> 2;        // n half (16 cols per gate)
    const int bn0 = blockIdx.x * 32;
    const int bm0 = blockIdx.y * 128;

    // ---- hoisted gate biases ----
    float bsr[2][2], bsz[2][2], bgn_[2][2], bhn_[2][2];
    #pragma unroll
    for (int ni = 0; ni < 2; ++ni)
        #pragma unroll
        for (int j = 0; j < 2; ++j){
            int col = bn0 + wn*16 + ni*8 + 2*(lane&3) + j;
            bsr[ni][j]  = g_bg[col] + bhh[col];
            bsz[ni][j]  = g_bg[HH + col] + bhh[HH + col];
            bgn_[ni][j] = g_bg[2*HH + col];
            bhn_[ni][j] = bhh[2*HH + col];
        }

    // ---- h tile cached in registers (this CTA exclusively owns it) ----
    float hreg[2][2][2][2];          // [mi][ph][ni][j]
    #pragma unroll
    for (int mi = 0; mi < 2; ++mi)
        #pragma unroll
        for (int ph = 0; ph < 2; ++ph){
            int r = bm0 + wm*32 + mi*16 + (lane>>2) + ph*8;
            #pragma unroll
            for (int ni = 0; ni < 2; ++ni){
                int colb = bn0 + wn*16 + ni*8 + 2*(lane&3);
                float2 v = *(const float2*)(g_hf + (size_t)r*HH + colb);
                hreg[mi][ph][ni][0] = v.x; hreg[mi][ph][ni][1] = v.y;
            }
        }

    #pragma unroll 1
    for (int t = 0; t < TT; ++t){
        const int src = t & 1, dst = src ^ 1;
        const __nv_bfloat16* aHiG = g_Ahi + (size_t)src*BN*HH;
        const __nv_bfloat16* aLoG = g_Alo + (size_t)src*BN*HH;
        const __nv_bfloat16* xHiG = g_Xhi + (size_t)t*BN*DIN;
        const __nv_bfloat16* xLoG = g_Xlo + (size_t)t*BN*DIN;

        // ---- staging helpers (c==16 means x chunk) ----
        auto stageA = [&](int c, int buf){
            const u32 sbase = sb + buf*BUFB;
            #pragma unroll
            for (int rep = 0; rep < 4; ++rep){
                int idx = rep*256 + tid;
                int plane = idx >> 9;              // 0=hi,1=lo
                int row = (idx >> 2) & 127;
                int seg = idx & 3;
                const __nv_bfloat16* g;
                if (c < 16){
                    const __nv_bfloat16* base = plane ? aLoG : aHiG;
                    g = base + (size_t)(bm0+row)*HH + c*32 + seg*8;
                } else {
                    const __nv_bfloat16* base = plane ? xLoG : xHiG;
                    g = base + (size_t)(bm0+row)*DIN + seg*8;
                }
                cp16(sbase + plane*APL + row*80 + seg*16, g);
            }
        };
        auto stageB = [&](int c, int buf){
            const u32 sbase = sb + buf*BUFB + OB;
            #pragma unroll
            for (int rep = 0; rep < 3; ++rep){
                int b = rep*256 + tid;
                int plane = (b >= 384) ? 1 : 0;
                int w = b - plane*384;
                int row = w >> 2;                  // 0..95
                int seg = w & 3;
                int gRow = (row >> 5)*HH + bn0 + (row & 31);
                const __nv_bfloat16* g;
                if (c < 16) g = (plane ? g_Bhlo : g_Bhhi) + (size_t)gRow*HH + c*32 + seg*8;
                else        g = (plane ? g_Bxlo : g_Bxhi) + (size_t)gRow*DIN + seg*8;
                cp16(sbase + plane*BPL + row*80 + seg*16, g);
            }
        };

        float acc[4][2][2][4];        // [r,z,nh,nx][mi][ni][frag]
        #pragma unroll
        for (int a = 0; a < 4; ++a)
            #pragma unroll
            for (int m = 0; m < 2; ++m)
                #pragma unroll
                for (int n = 0; n < 2; ++n)
                    #pragma unroll
                    for (int q = 0; q < 4; ++q) acc[a][m][n][q] = 0.f;

#define COMPUTE(BUF, XCHUNK)                                                  \
    {   const u32 sA = sb + (BUF)*BUFB;                                       \
        const u32 sB = sA + OB;                                               \
        _Pragma("unroll")                                                     \
        for (int kk = 0; kk < 2; ++kk){                                       \
            u32 aF[2][2][4];                                                  \
            _Pragma("unroll")                                                 \
            for (int mi = 0; mi < 2; ++mi){                                   \
                u32 rowa = wm*32 + mi*16 + ((lane>>3)&1)*8 + (lane&7);        \
                u32 off = rowa*80 + kk*32 + (lane>>4)*16;                     \
                ldm_x4(aF[0][mi], sA + off);                                  \
                ldm_x4(aF[1][mi], sA + APL + off);                            \
            }                                                                 \
            _Pragma("unroll")                                                 \
            for (int gate = 0; gate < 3; ++gate){                             \
                u32 bF[2][2][2];                                              \
                _Pragma("unroll")                                             \
                for (int ni = 0; ni < 2; ++ni){                               \
                    u32 rowb = gate*32 + wn*16 + ni*8 + (lane&7);             \
                    u32 off = rowb*80 + kk*32 + ((lane>>3)&1)*16;             \
                    ldm_x2(bF[0][ni], sB + off);                              \
                    ldm_x2(bF[1][ni], sB + BPL + off);                        \
                }                                                             \
                const int g2 = ((XCHUNK) && gate == 2) ? 3 : gate;            \
                _Pragma("unroll")                                             \
                for (int mi = 0; mi < 2; ++mi)                                \
                    _Pragma("unroll")                                         \
                    for (int ni = 0; ni < 2; ++ni){                           \
                        mma_bf16(acc[g2][mi][ni], aF[0][mi], bF[0][ni]);      \
                        mma_bf16(acc[g2][mi][ni], aF[1][mi], bF[0][ni]);      \
                        mma_bf16(acc[g2][mi][ni], aF[0][mi], bF[1][ni]);      \
                    }                                                         \
            }                                                                 \
        }                                                                     \
    }

        // ---- pre-barrier: x chunk (independent of h) + weights of chunk 0 ----
        stageA(16, 0); stageB(16, 0); CP_COMMIT();
        stageB(0, 1);  CP_COMMIT();
        CP_WAIT(1);
        __syncthreads();
        COMPUTE(0, 1)

        // ---- step barrier: previous step's h planes must be written ----
        if (t > 0 && tid == 0){
            const u32 target = (u32)t * 128u;
            u32 v;
            do {
                asm volatile("ld.acquire.gpu.global.b32 %0, [%1];"
                             : "=r"(v) : "l"(&g_bar) : "memory");
            } while (v < target);
        }
        __syncthreads();

        // ---- h chunks 0..15; buf(c) = (c+1)%3 ----
        stageA(0, 1); CP_COMMIT();
        #pragma unroll 1
        for (int c = 0; c < 16; ++c){
            if (c < 15){
                int nb = (c+2) % 3;
                stageA(c+1, nb); stageB(c+1, nb); CP_COMMIT();
                CP_WAIT(1);
            } else {
                CP_WAIT(0);
            }
            __syncthreads();
            const int cb = (c+1) % 3;
            COMPUTE(cb, 0)
        }
#undef COMPUTE

        // ---- epilogue: gates + h update (registers only) ----
        __nv_bfloat16* dHi = g_Ahi + (size_t)dst*BN*HH;
        __nv_bfloat16* dLo = g_Alo + (size_t)dst*BN*HH;
        const bool last = (t == TT-1);
        #pragma unroll
        for (int mi = 0; mi < 2; ++mi)
            #pragma unroll
            for (int ph = 0; ph < 2; ++ph){
                int r = bm0 + wm*32 + mi*16 + (lane>>2) + ph*8;
                #pragma unroll
                for (int ni = 0; ni < 2; ++ni){
                    int colb = bn0 + wn*16 + ni*8 + 2*(lane&3);
                    float hnew[2];
                    #pragma unroll
                    for (int j = 0; j < 2; ++j){
                        int q = ph*2 + j;
                        float r_ = sigm(acc[0][mi][ni][q] + bsr[ni][j]);
                        float z_ = sigm(acc[1][mi][ni][q] + bsz[ni][j]);
                        float n_ = tanh_(acc[3][mi][ni][q] + bgn_[ni][j]
                                         + r_*(acc[2][mi][ni][q] + bhn_[ni][j]));
                        float hv = hreg[mi][ph][ni][j];
                        hnew[j] = n_ + z_*(hv - n_);
                        hreg[mi][ph][ni][j] = hnew[j];
                    }
                    if (last){
                        *(float2*)(g_hf + (size_t)r*HH + colb) = make_float2(hnew[0], hnew[1]);
                    } else {
                        __nv_bfloat16 h0,l0,h1,l1;
                        split_bf16(hnew[0], h0, l0);
                        split_bf16(hnew[1], h1, l1);
                        *(__nv_bfloat162*)(dHi + (size_t)r*HH + colb) = __nv_bfloat162(h0, h1);
                        *(__nv_bfloat162*)(dLo + (size_t)r*HH + colb) = __nv_bfloat162(l0, l1);
                    }
                }
            }

        // ---- arrive (release h planes to other CTAs) ----
        __threadfence();
        __syncthreads();
        if (tid == 0) atomicAdd(&g_bar, 1u);
        // no wait here: next iteration's pre-barrier work is h-independent
    }
}

// ---------------- out2 = relu(relu(h) @ W3^T + b3) ----------------
__global__ void __launch_bounds__(256)
f1_kernel(const float* __restrict__ W3, const float* __restrict__ b3)
{
    __shared__ float As[16][68];
    __shared__ float Bs[16][68];
    const float* h = g_hf;
    int tid = threadIdx.x;
    int tx = tid & 15, ty = tid >> 4;
    int m0 = ty*4, n0 = tx*4;
    int bm0 = blockIdx.y*64, bn0 = blockIdx.x*64;
    int arow = tid >> 2, akq = (tid & 3) << 2;
    float acc[4][4] = {};
    for (int cc = 0; cc < HH/16; ++cc){
        int k0 = cc*16;
        float4 va = *(const float4*)(h  + (size_t)(bm0+arow)*HH + k0 + akq);
        va.x = fmaxf(va.x, 0.f); va.y = fmaxf(va.y, 0.f);
        va.z = fmaxf(va.z, 0.f); va.w = fmaxf(va.w, 0.f);
        float4 vb = *(const float4*)(W3 + (size_t)(bn0+arow)*HH + k0 + akq);
        __syncthreads();
        As[akq+0][arow] = va.x; As[akq+1][arow] = va.y;
        As[akq+2][arow] = va.z; As[akq+3][arow] = va.w;
        Bs[akq+0][arow] = vb.x; Bs[akq+1][arow] = vb.y;
        Bs[akq+2][arow] = vb.z; Bs[akq+3][arow] = vb.w;
        __syncthreads();
        #pragma unroll
        for (int k = 0; k < 16; ++k){
            float a[4], b[4];
            #pragma unroll
            for (int j = 0; j < 4; ++j){ a[j] = As[k][m0+j]; b[j] = Bs[k][n0+j]; }
            #pragma unroll
            for (int i = 0; i < 4; ++i)
                #pragma unroll
                for (int j = 0; j < 4; ++j)
                    acc[i][j] += a[i]*b[j];
        }
    }
    #pragma unroll
    for (int i = 0; i < 4; ++i){
        int row = bm0 + m0 + i;
        float4 o;
        o.x = fmaxf(acc[i][0] + b3[bn0+n0+0], 0.f);
        o.y = fmaxf(acc[i][1] + b3[bn0+n0+1], 0.f);
        o.z = fmaxf(acc[i][2] + b3[bn0+n0+2], 0.f);
        o.w = fmaxf(acc[i][3] + b3[bn0+n0+3], 0.f);
        *(float4*)(&g_out2[(size_t)row*DD2 + bn0 + n0]) = o;
    }
}

// ---------------- per-cultivar head + output write ----------------
__global__ void f2_kernel(const int* __restrict__ cult,
                          const float* __restrict__ Wh, const float* __restrict__ bh,
                          float* __restrict__ out)
{
    int b = blockIdx.x;
    int tid = threadIdx.x;
    __shared__ float s[DD2];
    s[tid] = g_out2[(size_t)b*DD2 + tid];
    __syncthreads();
    int c = cult[b];
    int o = tid >> 4, lane = tid & 15;
    const float* w = Wh + ((size_t)c*DOUT + o)*DD2;
    float acc = 0.f;
    for (int k = lane; k < DD2; k += 16) acc += s[k]*w[k];
    #pragma unroll
    for (int off = 8; off; off >>= 1) acc += __shfl_down_sync(0xffffffffu, acc, off, 16);
    if (lane == 0) out[(size_t)b*DOUT + o] = acc + bh[c*DOUT + o];
    for (int i = tid; i < HH; i += 256)
        out[(size_t)BN*DOUT + (size_t)b*HH + i] = g_hf[(size_t)b*HH + i];
}

// ---------------- launcher ----------------
extern "C" void kernel_launch(void* const* d_in, const int* in_sizes, int n_in,
                              void* d_out, int out_size)
{
    const float* input = (const float*)d_in[0];
    const float* hn    = (const float*)d_in[1];
    const int*   cult  = (const int*)d_in[2];
    const float* W1    = (const float*)d_in[3];
    const float* b1    = (const float*)d_in[4];
    const float* W2    = (const float*)d_in[5];
    const float* b2    = (const float*)d_in[6];
    const float* W_ih  = (const float*)d_in[7];
    const float* W_hh  = (const float*)d_in[8];
    const float* b_ih  = (const float*)d_in[9];
    const float* b_hh  = (const float*)d_in[10];
    const float* W3    = (const float*)d_in[11];
    const float* b3    = (const float*)d_in[12];
    const float* Wh    = (const float*)d_in[13];
    const float* bh    = (const float*)d_in[14];
    float* out = (float*)d_out;

    cudaFuncSetAttribute(gru_persist, cudaFuncAttributeMaxDynamicSharedMemorySize, SMEM_STEP);

    fold1<<<HH, 32>>>(W2, W1, b1, b2);
    fold2<<<GG, 32>>>(W_ih, b_ih);
    packBh<<<(GG*HH + 255)/256, 256>>>(W_hh);
    packBx<<<(GG*DIN + 255)/256, 256>>>();
    packX<<<(TT*BN*DIN + 255)/256, 256>>>(input);
    copyh<<<(BN*HH + 255)/256, 256>>>(hn);

    gru_persist<<<dim3(16, 8), 256, SMEM_STEP>>>(b_hh);

    f1_kernel<<<dim3(DD2/64, BN/64), 256>>>(W3, b3);
    f2_kernel<<<BN, 256>>>(cult, Wh, bh, out);
}